// round 1
// baseline (speedup 1.0000x reference)
#include <cuda_runtime.h>

// Problem shapes (fixed per reference setup_inputs)
#define BB 32
#define HH 1024
#define WW 1024
#define TH 512
#define TW 512
#define SS 256
#define BAND_ROWS 16      // output rows per block
#define NBANDS (HH / BAND_ROWS)  // 64

__device__ double g_img_sum;
__device__ double g_stn_sum;

__global__ void init_kernel() {
    g_img_sum = 0.0;
    g_stn_sum = 0.0;
}

// One block = (band of 16 output rows) x (one batch image), 256 threads.
// Each thread owns a 4-wide column quad (x = 4t..4t+3) across all 16 rows.
// Target rows kbase..kbase+9 staged in SMEM; thread keeps rolling 3x4 register
// window of the 4 target columns it needs (2t-1..2t+2, clamped).
__global__ __launch_bounds__(256) void img_kernel(const float* __restrict__ pred,
                                                  const float* __restrict__ tgt) {
    __shared__ float st[10][TW];   // 20 KB
    __shared__ float wsum[8];

    const int band = blockIdx.x;   // 0..63
    const int b    = blockIdx.y;   // 0..31
    const int tid  = threadIdx.x;  // 0..255
    const int kbase = band * 8 - 1;

    // Phase A: stage 10 target rows (row-clamped at image edges)
    const float* tb = tgt + (size_t)b * TH * TW;
#pragma unroll
    for (int i = 0; i < 5; ++i) {
        int idx = tid + i * 256;          // 0..1279 float4 slots
        int r   = idx >> 7;               // 0..9
        int c4  = (idx & 127) << 2;       // 0..508
        int k   = kbase + r;
        k = k < 0 ? 0 : (k > TH - 1 ? TH - 1 : k);
        float4 v = *(const float4*)(tb + (size_t)k * TW + c4);
        *(float4*)&st[r][c4] = v;
    }
    __syncthreads();

    // Column indices this thread needs (target cols 2t-1..2t+2, clamped)
    const int t = tid;
    int j0 = 2 * t - 1; if (j0 < 0) j0 = 0;
    const int j1 = 2 * t;
    const int j2 = 2 * t + 1;
    int j3 = 2 * t + 2; if (j3 > TW - 1) j3 = TW - 1;

    float a0 = st[0][j0], a1 = st[0][j1], a2 = st[0][j2], a3 = st[0][j3];
    float b0 = st[1][j0], b1 = st[1][j1], b2 = st[1][j2], b3 = st[1][j3];

    const float* pb = pred + ((size_t)b * HH + (size_t)band * BAND_ROWS) * WW + 4 * t;
    float acc = 0.f;

#pragma unroll
    for (int p = 0; p < 8; ++p) {
        // next target row into c-regs
        float c0 = st[p + 2][j0], c1 = st[p + 2][j1];
        float c2 = st[p + 2][j2], c3 = st[p + 2][j3];

        // even output row (weights 0.25 on row p, 0.75 on row p+1)
        float4 pv = *(const float4*)(pb + (size_t)(2 * p) * WW);
        float v0 = 0.25f * a0 + 0.75f * b0;
        float v1 = 0.25f * a1 + 0.75f * b1;
        float v2 = 0.25f * a2 + 0.75f * b2;
        float v3 = 0.25f * a3 + 0.75f * b3;
        float d;
        d = pv.x - (0.25f * v0 + 0.75f * v1); acc = fmaf(d, d, acc);
        d = pv.y - (0.75f * v1 + 0.25f * v2); acc = fmaf(d, d, acc);
        d = pv.z - (0.25f * v1 + 0.75f * v2); acc = fmaf(d, d, acc);
        d = pv.w - (0.75f * v2 + 0.25f * v3); acc = fmaf(d, d, acc);

        // odd output row (weights 0.75 on row p+1, 0.25 on row p+2)
        pv = *(const float4*)(pb + (size_t)(2 * p + 1) * WW);
        v0 = 0.75f * b0 + 0.25f * c0;
        v1 = 0.75f * b1 + 0.25f * c1;
        v2 = 0.75f * b2 + 0.25f * c2;
        v3 = 0.75f * b3 + 0.25f * c3;
        d = pv.x - (0.25f * v0 + 0.75f * v1); acc = fmaf(d, d, acc);
        d = pv.y - (0.75f * v1 + 0.25f * v2); acc = fmaf(d, d, acc);
        d = pv.z - (0.25f * v1 + 0.75f * v2); acc = fmaf(d, d, acc);
        d = pv.w - (0.75f * v2 + 0.25f * v3); acc = fmaf(d, d, acc);

        // roll window
        a0 = b0; a1 = b1; a2 = b2; a3 = b3;
        b0 = c0; b1 = c1; b2 = c2; b3 = c3;
    }

    // block reduction -> one double atomic per block
#pragma unroll
    for (int o = 16; o > 0; o >>= 1)
        acc += __shfl_xor_sync(0xffffffffu, acc, o);
    int lane = tid & 31, wid = tid >> 5;
    if (lane == 0) wsum[wid] = acc;
    __syncthreads();
    if (tid == 0) {
        float s = 0.f;
#pragma unroll
        for (int i = 0; i < 8; ++i) s += wsum[i];
        atomicAdd(&g_img_sum, (double)s);
    }
}

// 8192 stations, 3x3 masked box mean around (row=py, col=px), MSE vs runoff.
__global__ __launch_bounds__(256) void stn_kernel(const float* __restrict__ pred,
                                                  const int* __restrict__ pos,
                                                  const float* __restrict__ run) {
    __shared__ float wsum[8];
    int idx = blockIdx.x * 256 + threadIdx.x;  // 0..8191
    int b = idx >> 8;
    int px = pos[2 * idx];       // column
    int py = pos[2 * idx + 1];   // row
    const float* pb = pred + (size_t)b * HH * WW;

    float sum = 0.f;
    int cnt = 0;
#pragma unroll
    for (int dy = -1; dy <= 1; ++dy) {
        int y = py + dy;
        if ((unsigned)y < (unsigned)HH) {
#pragma unroll
            for (int dx = -1; dx <= 1; ++dx) {
                int x = px + dx;
                if ((unsigned)x < (unsigned)WW) {
                    sum += pb[(size_t)y * WW + x];
                    cnt++;
                }
            }
        }
    }
    float d = sum / (float)cnt - run[idx];
    float v = d * d;

#pragma unroll
    for (int o = 16; o > 0; o >>= 1)
        v += __shfl_xor_sync(0xffffffffu, v, o);
    int lane = threadIdx.x & 31, wid = threadIdx.x >> 5;
    if (lane == 0) wsum[wid] = v;
    __syncthreads();
    if (threadIdx.x == 0) {
        float s = 0.f;
#pragma unroll
        for (int i = 0; i < 8; ++i) s += wsum[i];
        atomicAdd(&g_stn_sum, (double)s);
    }
}

__global__ void final_kernel(float* __restrict__ out) {
    double img = g_img_sum / (double)((size_t)BB * HH * WW);
    double stn = g_stn_sum / (double)(BB * SS);
    out[0] = (float)(img + 0.5 * stn);  // IMAGE_W=1.0, STATION_W=0.5
    out[1] = (float)img;
    out[2] = (float)stn;
}

extern "C" void kernel_launch(void* const* d_in, const int* in_sizes, int n_in,
                              void* d_out, int out_size) {
    const float* pred = (const float*)d_in[0];   // (32,1,1024,1024) f32
    const float* tgt  = (const float*)d_in[1];   // (32,1,512,512) f32
    const int*   pos  = (const int*)d_in[2];     // (32,256,2) i32
    const float* run  = (const float*)d_in[3];   // (32,256) f32
    float* out = (float*)d_out;

    init_kernel<<<1, 1>>>();
    img_kernel<<<dim3(NBANDS, BB), 256>>>(pred, tgt);
    stn_kernel<<<BB, 256>>>(pred, pos, run);
    final_kernel<<<1, 1>>>(out);
}